// round 8
// baseline (speedup 1.0000x reference)
#include <cuda_runtime.h>

#define BB   8
#define NN   128
#define COOR 3
#define FF   128
#define FILT 128

// Scratch: A' = x @ w1 + bv  and  C = x @ w2, each [B, N, COOR, FILT]
__device__ float g_A[BB * NN * COOR * FILT];
__device__ float g_C[BB * NN * COOR * FILT];

// ---- packed f32x2 helpers --------------------------------------------------
typedef unsigned long long ull;

union F4U {
    float4 f4;
    ull    u[2];
};
union F2U {
    float2 f2;
    ull    u;
};

__device__ __forceinline__ ull fma2(ull a, ull b, ull c) {
    ull r;
    asm("fma.rn.f32x2 %0, %1, %2, %3;" : "=l"(r) : "l"(a), "l"(b), "l"(c));
    return r;
}
__device__ __forceinline__ ull add2(ull a, ull b) {
    ull r;
    asm("add.rn.f32x2 %0, %1, %2;" : "=l"(r) : "l"(a), "l"(b));
    return r;
}
__device__ __forceinline__ ull mul2(ull a, ull b) {
    ull r;
    asm("mul.rn.f32x2 %0, %1, %2;" : "=l"(r) : "l"(a), "l"(b));
    return r;
}
__device__ __forceinline__ ull pack2(float lo, float hi) {
    ull r;
    asm("mov.b64 %0, {%1, %2};" : "=l"(r) : "r"(__float_as_uint(lo)), "r"(__float_as_uint(hi)));
    return r;
}

// ---------------------------------------------------------------------------
// Phase 1: tiny GEMM [3072, 128] @ [128, 256]  ->  g_A (with +bv), g_C
// R7 post-mortem: 196 MB of redundant w L2 reads (every warp reloaded the
// block's w-half) made p1 L2-BW-bound at ~11.4us. Fix: stage the 64 KB
// w-half in SMEM ONCE per block (chip w-traffic 196 -> 24.5 MB), with
// w1/w2 interleaved 16B/lane (inner loop = one conflict-free LDS.128) and
// the x-tile pre-duplicated into 64-bit lane pairs (zero pack MOVs).
// Inner loop per f: 1 LDS.128 + 4 LDS.64 + 8 FFMA2 = 13 instr.
// RT=16 rows, KH=64, grid (192,2)=384 blocks, 128 thr; 80 KB dynamic smem.
// ---------------------------------------------------------------------------
__global__ __launch_bounds__(128) void phase1_kernel(
    const float* __restrict__ x,   // [3072, 128]
    const float* __restrict__ w,   // [256, 128]
    const float* __restrict__ bv)  // [128]
{
    constexpr int RT = 16;               // rows per block
    constexpr int KH = 64;               // k per block
    const int r0   = blockIdx.x * RT;
    const int kh   = blockIdx.y * KH;
    const int warp = threadIdx.x >> 5;   // 0..3
    const int lane = threadIdx.x & 31;
    const int k    = kh + lane * 2;      // this thread's k-pair
    const int wr   = warp * 4;           // first of this warp's 4 rows

    extern __shared__ char smem[];
    float4* ws  = reinterpret_cast<float4*>(smem);            // [128][32] = 64 KB
    ull*    xs2 = reinterpret_cast<ull*>(smem + 65536);       // [16][128] = 16 KB

    // Stage w-half interleaved: ws[f*32 + l] = (w1[f][kh+2l], w1[f][kh+2l+1],
    //                                           w2[f][kh+2l], w2[f][kh+2l+1])
    {
        #pragma unroll
        for (int t = threadIdx.x; t < FF * 32; t += 128) {
            const int f = t >> 5;
            const int l = t & 31;
            const float2 a = *reinterpret_cast<const float2*>(w + (size_t)f * FILT + kh + 2 * l);
            const float2 b = *reinterpret_cast<const float2*>(w + (size_t)(FF + f) * FILT + kh + 2 * l);
            ws[t] = make_float4(a.x, a.y, b.x, b.y);
        }
    }
    // Stage x-tile pre-duplicated: xs2[row*128 + f] = (x, x) packed.
    {
        const float4* xin = reinterpret_cast<const float4*>(x + (size_t)r0 * FF);
        #pragma unroll
        for (int t = threadIdx.x; t < RT * FF / 4; t += 128) {
            const float4 v = xin[t];
            ulonglong2* dst = reinterpret_cast<ulonglong2*>(&xs2[4 * t]);
            dst[0] = make_ulonglong2(pack2(v.x, v.x), pack2(v.y, v.y));
            dst[1] = make_ulonglong2(pack2(v.z, v.z), pack2(v.w, v.w));
        }
    }
    __syncthreads();

    ull acc[4][2];   // [row][A/C]
    {
        const float2 b2 = *reinterpret_cast<const float2*>(bv + k);
        const ull bp = pack2(b2.x, b2.y);
        #pragma unroll
        for (int r = 0; r < 4; r++) { acc[r][0] = bp; acc[r][1] = 0ull; }
    }

    #pragma unroll 4
    for (int f = 0; f < FF; f++) {
        F4U wv;
        wv.f4 = ws[f * 32 + lane];           // LDS.128, conflict-free
        const ull w1v = wv.u[0];
        const ull w2v = wv.u[1];
        #pragma unroll
        for (int r = 0; r < 4; r++) {
            const ull xp = xs2[(wr + r) * FF + f];   // LDS.64 broadcast, pre-packed
            acc[r][0] = fma2(xp, w1v, acc[r][0]);
            acc[r][1] = fma2(xp, w2v, acc[r][1]);
        }
    }

    #pragma unroll
    for (int r = 0; r < 4; r++) {
        const size_t row = (size_t)(r0 + wr + r);
        F2U oa; oa.u = acc[r][0];
        F2U oc; oc.u = acc[r][1];
        *reinterpret_cast<float2*>(&g_A[row * FILT + k]) = oa.f2;
        *reinterpret_cast<float2*>(&g_C[row * FILT + k]) = oc.f2;
    }
}

// ---------------------------------------------------------------------------
// Phase 2: out[b,i,j,k] = sum_c (A'[b,i,c,k] + C[b,j,c,k]) * d[b,i,j,c]
// Proven 256-block single-wave config, now with PRE-PACKED f32x2 math:
// distances are duplicated into 64-bit pairs at smem-fill time (4-slot
// padding so (dp0,dp1) is one aligned LDS.128), C and A' alias packed
// halves through unions -> ZERO runtime pack MOVs (R3's failure mode).
// Per j-iter: 3 LDG.128 (C, prefetched) + 4x(2 LDS + 12 packed ops + STG).
// ---------------------------------------------------------------------------
__global__ __launch_bounds__(256) void phase2_kernel(
    const float* __restrict__ dist,  // [B, N, N, COOR]
    float* __restrict__ out)         // [B, N, N, FILT]
{
    constexpr int TI = 4;
    const int b  = blockIdx.y;
    const int i0 = blockIdx.x * TI;
    const int tx = threadIdx.x;   // 0..31
    const int ty = threadIdx.y;   // 0..7
    const int tid = ty * 32 + tx;

    __shared__ ull sdp[TI * NN * 4];   // (i,j) -> 4 slots (d0,d1,d2,pad): 16 KB

    // Fill pre-packed distances: sdp[(i*NN+j)*4 + c] = (d, d).
    {
        const float* dbase = dist + (size_t)(b * NN + i0) * NN * COOR;
        #pragma unroll
        for (int e = tid; e < TI * NN * COOR; e += 256) {
            const float v = dbase[e];               // coalesced LDG.32
            sdp[(e / COOR) * 4 + (e % COOR)] = pack2(v, v);
        }
    }

    // A' tile into registers (packed halves via union): 48 regs.
    F4U Ar[TI][COOR];
    {
        const float4* A4 = reinterpret_cast<const float4*>(g_A);
        #pragma unroll
        for (int i = 0; i < TI; i++)
            #pragma unroll
            for (int c = 0; c < COOR; c++)
                Ar[i][c].f4 = A4[((size_t)(b * NN + i0 + i) * COOR + c) * (FILT / 4) + tx];
    }
    __syncthreads();

    const float4* C4 = reinterpret_cast<const float4*>(g_C) +
                       (size_t)b * NN * COOR * (FILT / 4) + tx;
    float4* out4 = reinterpret_cast<float4*>(out) +
                   ((size_t)(b * NN + i0) * NN) * (FILT / 4) + tx;

    // Prime C pipeline with j = ty.
    F4U c0, c1, c2;
    c0.f4 = C4[(size_t)ty * COOR * (FILT / 4) + 0 * (FILT / 4)];
    c1.f4 = C4[(size_t)ty * COOR * (FILT / 4) + 1 * (FILT / 4)];
    c2.f4 = C4[(size_t)ty * COOR * (FILT / 4) + 2 * (FILT / 4)];

    #pragma unroll
    for (int it = 0; it < NN / 8; it++) {
        const int j = ty + it * 8;

        F4U n0, n1, n2;
        if (it + 1 < NN / 8) {
            const size_t nb = (size_t)(j + 8) * COOR * (FILT / 4);
            n0.f4 = C4[nb + 0 * (FILT / 4)];
            n1.f4 = C4[nb + 1 * (FILT / 4)];
            n2.f4 = C4[nb + 2 * (FILT / 4)];
        }

        #pragma unroll
        for (int i = 0; i < TI; i++) {
            const int sb = (i * NN + j) * 4;
            // (dp0, dp1) in one aligned LDS.128, dp2 as LDS.64 — all broadcast.
            const ulonglong2 d01 = *reinterpret_cast<const ulonglong2*>(&sdp[sb]);
            const ull dp0 = d01.x, dp1 = d01.y;
            const ull dp2 = sdp[sb + 2];

            const ull a0l = add2(Ar[i][0].u[0], c0.u[0]);
            const ull a0h = add2(Ar[i][0].u[1], c0.u[1]);
            const ull a1l = add2(Ar[i][1].u[0], c1.u[0]);
            const ull a1h = add2(Ar[i][1].u[1], c1.u[1]);
            const ull a2l = add2(Ar[i][2].u[0], c2.u[0]);
            const ull a2h = add2(Ar[i][2].u[1], c2.u[1]);

            F4U o;
            o.u[0] = fma2(a0l, dp0, fma2(a1l, dp1, mul2(a2l, dp2)));
            o.u[1] = fma2(a0h, dp0, fma2(a1h, dp1, mul2(a2h, dp2)));

            out4[((size_t)i * NN + j) * (FILT / 4)] = o.f4;
        }

        c0 = n0; c1 = n1; c2 = n2;
    }
}

extern "C" void kernel_launch(void* const* d_in, const int* in_sizes, int n_in,
                              void* d_out, int out_size)
{
    const float* x    = (const float*)d_in[0];  // vector_features [8,128,3,128]
    const float* dist = (const float*)d_in[1];  // distances       [8,128,128,3]
    const float* w    = (const float*)d_in[2];  // w_vs            [256,128]
    const float* bv   = (const float*)d_in[3];  // b_vs            [128]
    float* out = (float*)d_out;                 // [8,128,128,128]

    (void)in_sizes; (void)n_in; (void)out_size;

    const int p1_smem = 65536 + 16384;   // ws (64 KB) + xs2 (16 KB)
    cudaFuncSetAttribute(phase1_kernel,
                         cudaFuncAttributeMaxDynamicSharedMemorySize, p1_smem);

    phase1_kernel<<<dim3((BB * NN * COOR) / 16, 2), 128, p1_smem>>>(x, w, bv);
    phase2_kernel<<<dim3(NN / 4, BB), dim3(32, 8)>>>(dist, out);
}

// round 9
// speedup vs baseline: 1.0865x; 1.0865x over previous
#include <cuda_runtime.h>

#define BB   8
#define NN   128
#define COOR 3
#define FF   128
#define FILT 128

// Scratch: A' = x @ w1 + bv  and  C = x @ w2, each [B, N, COOR, FILT]
__device__ float g_A[BB * NN * COOR * FILT];
__device__ float g_C[BB * NN * COOR * FILT];

// ---- packed f32x2 helpers (PHASE 1 ONLY — banned from phase 2) ------------
typedef unsigned long long ull;

union F2U {
    float2 f2;
    ull    u;
};

__device__ __forceinline__ ull fma2(ull a, ull b, ull c) {
    ull r;
    asm("fma.rn.f32x2 %0, %1, %2, %3;" : "=l"(r) : "l"(a), "l"(b), "l"(c));
    return r;
}
__device__ __forceinline__ ull pack2(float lo, float hi) {
    ull r;
    asm("mov.b64 %0, {%1, %2};" : "=l"(r) : "r"(__float_as_uint(lo)), "r"(__float_as_uint(hi)));
    return r;
}

// ---------------------------------------------------------------------------
// Phase 1: tiny GEMM [3072, 128] @ [128, 256]  ->  g_A (with +bv), g_C
// Traffic law (validated R7): w L2-traffic = 393/R MB, R = rows/warp.
// R7: R=2 -> 196 MB -> 11.4us (L2-BW bound). Here R=8 -> 49 MB (~3.9us),
// via the PROVEN R7 mechanism: register DEPTH-8 rotating w-prefetch
// (covers ~250cyc L2 latency), x pre-packed (f32x2 pairs) in smem.
// Block = 64 thr (2 warps x 8 rows = 16 rows), grid (192, 2) = 384 blocks
// = 768 warps = 5.2 warps/SM. Per f-iter: 2 LDG.64 + 8 LDS.64(bcast)
// + 16 FFMA2 = 26 instr. Issue floor ~2.2us; L2 ~3.9us -> predict ~5us.
// ---------------------------------------------------------------------------
__global__ __launch_bounds__(64) void phase1_kernel(
    const float* __restrict__ x,   // [3072, 128]
    const float* __restrict__ w,   // [256, 128]
    const float* __restrict__ bv)  // [128]
{
    constexpr int WR    = 8;             // rows per warp
    constexpr int RT    = 16;            // rows per block (2 warps)
    constexpr int DEPTH = 8;             // w-prefetch pipeline depth
    const int r0   = blockIdx.x * RT;
    const int kh   = blockIdx.y * 64;    // k half
    const int warp = threadIdx.x >> 5;   // 0..1
    const int lane = threadIdx.x & 31;
    const int k    = kh + lane * 2;      // this thread's k-pair
    const int wr   = warp * WR;          // first of this warp's 8 rows

    __shared__ ull xs2[RT * FF];         // pre-packed (x,x) pairs: 16 KB

    // Stage x-tile pre-duplicated: xs2[row*128 + f] = (x, x).
    {
        const float4* xin = reinterpret_cast<const float4*>(x + (size_t)r0 * FF);
        #pragma unroll
        for (int t = threadIdx.x; t < RT * FF / 4; t += 64) {
            const float4 v = xin[t];
            ulonglong2* dst = reinterpret_cast<ulonglong2*>(&xs2[4 * t]);
            dst[0] = make_ulonglong2(pack2(v.x, v.x), pack2(v.y, v.y));
            dst[1] = make_ulonglong2(pack2(v.z, v.z), pack2(v.w, v.w));
        }
    }
    __syncthreads();

    ull accA[WR], accC[WR];
    {
        const float2 b2 = *reinterpret_cast<const float2*>(bv + k);
        const ull bp = pack2(b2.x, b2.y);
        #pragma unroll
        for (int r = 0; r < WR; r++) { accA[r] = bp; accC[r] = 0ull; }
    }

    const float* w1base = w + k;
    const float* w2base = w + (size_t)FF * FILT + k;

    // Prime the depth-8 rotating pipeline.
    F2U W1[DEPTH], W2[DEPTH];
    #pragma unroll
    for (int d = 0; d < DEPTH; d++) {
        W1[d].f2 = *reinterpret_cast<const float2*>(w1base + (size_t)d * FILT);
        W2[d].f2 = *reinterpret_cast<const float2*>(w2base + (size_t)d * FILT);
    }

    const ull* xrow = &xs2[wr * FF];

    #pragma unroll 8   // = DEPTH, so f % DEPTH is a compile-time slot index
    for (int f = 0; f < FF; f++) {
        const int slot = f % DEPTH;
        const ull w1v = W1[slot].u;
        const ull w2v = W2[slot].u;

        #pragma unroll
        for (int r = 0; r < WR; r++) {
            const ull xp = xrow[r * FF + f];   // LDS.64 broadcast, pre-packed
            accA[r] = fma2(xp, w1v, accA[r]);
            accC[r] = fma2(xp, w2v, accC[r]);
        }

        // Refill this slot for iteration f + DEPTH.
        if (f + DEPTH < FF) {
            W1[slot].f2 = *reinterpret_cast<const float2*>(w1base + (size_t)(f + DEPTH) * FILT);
            W2[slot].f2 = *reinterpret_cast<const float2*>(w2base + (size_t)(f + DEPTH) * FILT);
        }
    }

    #pragma unroll
    for (int r = 0; r < WR; r++) {
        const size_t row = (size_t)(r0 + wr + r);
        F2U oa; oa.u = accA[r];
        F2U oc; oc.u = accC[r];
        *reinterpret_cast<float2*>(&g_A[row * FILT + k]) = oa.f2;
        *reinterpret_cast<float2*>(&g_C[row * FILT + k]) = oc.f2;
    }
}

// ---------------------------------------------------------------------------
// Phase 2: out[b,i,j,k] = sum_c (A'[b,i,c,k] + C[b,j,c,k]) * d[b,i,j,c]
// Proven R4 scalar skeleton (TI=4, 256 blocks, single wave), but the
// 1-ahead prefetch (issue stuck at 28%) is replaced by TWO INDEPENDENT
// j-chains per iteration (j and j+64): 6 C-loads issue back-to-back ->
// 2x memory-level parallelism per warp; chain B's latency is covered by
// chain A's compute. Scalar FMA only (packed failed 3/3 rounds here).
// ---------------------------------------------------------------------------
__global__ __launch_bounds__(256) void phase2_kernel(
    const float* __restrict__ dist,  // [B, N, N, COOR]
    float* __restrict__ out)         // [B, N, N, FILT]
{
    constexpr int TI = 4;
    const int b  = blockIdx.y;
    const int i0 = blockIdx.x * TI;
    const int tx = threadIdx.x;   // 0..31
    const int ty = threadIdx.y;   // 0..7
    const int tid = ty * 32 + tx;

    __shared__ float4 sd4[TI * NN];   // padded (d0,d1,d2,_) per (i,j): 8 KB

    {
        const float* dbase = dist + (size_t)(b * NN + i0) * NN * COOR;
        #pragma unroll
        for (int t = tid; t < TI * NN; t += 256) {
            const int e = t * COOR;
            sd4[t] = make_float4(dbase[e], dbase[e + 1], dbase[e + 2], 0.0f);
        }
    }

    float4 Ar[TI][COOR];
    {
        const float4* A4 = reinterpret_cast<const float4*>(g_A);
        #pragma unroll
        for (int i = 0; i < TI; i++)
            #pragma unroll
            for (int c = 0; c < COOR; c++)
                Ar[i][c] = A4[((size_t)(b * NN + i0 + i) * COOR + c) * (FILT / 4) + tx];
    }
    __syncthreads();

    const float4* C4 = reinterpret_cast<const float4*>(g_C) +
                       (size_t)b * NN * COOR * (FILT / 4) + tx;
    float4* out4 = reinterpret_cast<float4*>(out) +
                   ((size_t)(b * NN + i0) * NN) * (FILT / 4) + tx;

    #pragma unroll
    for (int it = 0; it < NN / 16; it++) {
        const int jA = ty + it * 8;        // 0..63
        const int jB = jA + 64;            // 64..127

        // Two independent load chains, issued together (6 LDG.128 in flight).
        const size_t ca = (size_t)jA * COOR * (FILT / 4);
        const size_t cb = (size_t)jB * COOR * (FILT / 4);
        const float4 a0 = C4[ca + 0 * (FILT / 4)];
        const float4 a1 = C4[ca + 1 * (FILT / 4)];
        const float4 a2 = C4[ca + 2 * (FILT / 4)];
        const float4 b0 = C4[cb + 0 * (FILT / 4)];
        const float4 b1 = C4[cb + 1 * (FILT / 4)];
        const float4 b2 = C4[cb + 2 * (FILT / 4)];

        #pragma unroll
        for (int i = 0; i < TI; i++) {
            const float4 dv = sd4[i * NN + jA];   // one LDS.128 broadcast
            const float d0 = dv.x, d1 = dv.y, d2 = dv.z;
            float4 o;
            o.x = fmaf(Ar[i][0].x + a0.x, d0,
                  fmaf(Ar[i][1].x + a1.x, d1, (Ar[i][2].x + a2.x) * d2));
            o.y = fmaf(Ar[i][0].y + a0.y, d0,
                  fmaf(Ar[i][1].y + a1.y, d1, (Ar[i][2].y + a2.y) * d2));
            o.z = fmaf(Ar[i][0].z + a0.z, d0,
                  fmaf(Ar[i][1].z + a1.z, d1, (Ar[i][2].z + a2.z) * d2));
            o.w = fmaf(Ar[i][0].w + a0.w, d0,
                  fmaf(Ar[i][1].w + a1.w, d1, (Ar[i][2].w + a2.w) * d2));
            out4[((size_t)i * NN + jA) * (FILT / 4)] = o;
        }

        #pragma unroll
        for (int i = 0; i < TI; i++) {
            const float4 dv = sd4[i * NN + jB];
            const float d0 = dv.x, d1 = dv.y, d2 = dv.z;
            float4 o;
            o.x = fmaf(Ar[i][0].x + b0.x, d0,
                  fmaf(Ar[i][1].x + b1.x, d1, (Ar[i][2].x + b2.x) * d2));
            o.y = fmaf(Ar[i][0].y + b0.y, d0,
                  fmaf(Ar[i][1].y + b1.y, d1, (Ar[i][2].y + b2.y) * d2));
            o.z = fmaf(Ar[i][0].z + b0.z, d0,
                  fmaf(Ar[i][1].z + b1.z, d1, (Ar[i][2].z + b2.z) * d2));
            o.w = fmaf(Ar[i][0].w + b0.w, d0,
                  fmaf(Ar[i][1].w + b1.w, d1, (Ar[i][2].w + b2.w) * d2));
            out4[((size_t)i * NN + jB) * (FILT / 4)] = o;
        }
    }
}

extern "C" void kernel_launch(void* const* d_in, const int* in_sizes, int n_in,
                              void* d_out, int out_size)
{
    const float* x    = (const float*)d_in[0];  // vector_features [8,128,3,128]
    const float* dist = (const float*)d_in[1];  // distances       [8,128,128,3]
    const float* w    = (const float*)d_in[2];  // w_vs            [256,128]
    const float* bv   = (const float*)d_in[3];  // b_vs            [128]
    float* out = (float*)d_out;                 // [8,128,128,128]

    (void)in_sizes; (void)n_in; (void)out_size;

    phase1_kernel<<<dim3((BB * NN * COOR) / 16, 2), 64>>>(x, w, bv);
    phase2_kernel<<<dim3(NN / 4, BB), dim3(32, 8)>>>(dist, out);
}